// round 2
// baseline (speedup 1.0000x reference)
#include <cuda_runtime.h>

static constexpr int V = 1024;

__global__ void zero_out_kernel(float* out) {
    if (threadIdx.x == 0) out[0] = 0.0f;
}

__global__ void loss_kernel(const float* __restrict__ pred,
                            const int* __restrict__ tgt,
                            float* __restrict__ out, int B) {
    int i = blockIdx.x * blockDim.x + threadIdx.x;
    float v = 0.0f;
    if (i < B) {
        int t = tgt[i];
        float p = __ldg(&pred[(size_t)i * V + t]);
        v = -__logf(p);
    }
    // warp reduction
    #pragma unroll
    for (int o = 16; o > 0; o >>= 1)
        v += __shfl_down_sync(0xffffffffu, v, o);

    __shared__ float smem[32];
    int lane = threadIdx.x & 31;
    int warp = threadIdx.x >> 5;
    if (lane == 0) smem[warp] = v;
    __syncthreads();

    if (warp == 0) {
        int nwarps = (blockDim.x + 31) >> 5;
        v = (lane < nwarps) ? smem[lane] : 0.0f;
        #pragma unroll
        for (int o = 16; o > 0; o >>= 1)
            v += __shfl_down_sync(0xffffffffu, v, o);
        if (lane == 0) atomicAdd(out, v);
    }
}

extern "C" void kernel_launch(void* const* d_in, const int* in_sizes, int n_in,
                              void* d_out, int out_size) {
    const float* pred = (const float*)d_in[0];
    const int* tgt = (const int*)d_in[1];
    float* out = (float*)d_out;
    int B = in_sizes[1];  // number of targets (rows)

    zero_out_kernel<<<1, 32>>>(out);

    const int threads = 256;
    int blocks = (B + threads - 1) / threads;
    loss_kernel<<<blocks, threads>>>(pred, tgt, out, B);
}

// round 3
// speedup vs baseline: 1.0332x; 1.0332x over previous
#include <cuda_runtime.h>

static constexpr int V = 1024;

__global__ void zero_out_kernel(float* out) {
    if (threadIdx.x == 0) out[0] = 0.0f;
}

__global__ void loss_kernel(const float* __restrict__ pred,
                            const int* __restrict__ tgt,
                            float* __restrict__ out, int B) {
    int i = blockIdx.x * blockDim.x + threadIdx.x;
    float v = 0.0f;
    if (i < B) {
        int t = __ldcg(&tgt[i]);
        // L2-only gather: avoid the 128B line fill the nc path was doing
        float p = __ldcg(&pred[(size_t)i * V + t]);
        v = -__logf(p);
    }
    // warp reduction
    #pragma unroll
    for (int o = 16; o > 0; o >>= 1)
        v += __shfl_down_sync(0xffffffffu, v, o);

    __shared__ float smem[32];
    int lane = threadIdx.x & 31;
    int warp = threadIdx.x >> 5;
    if (lane == 0) smem[warp] = v;
    __syncthreads();

    if (warp == 0) {
        int nwarps = (blockDim.x + 31) >> 5;
        v = (lane < nwarps) ? smem[lane] : 0.0f;
        #pragma unroll
        for (int o = 16; o > 0; o >>= 1)
            v += __shfl_down_sync(0xffffffffu, v, o);
        if (lane == 0) atomicAdd(out, v);
    }
}

extern "C" void kernel_launch(void* const* d_in, const int* in_sizes, int n_in,
                              void* d_out, int out_size) {
    const float* pred = (const float*)d_in[0];
    const int* tgt = (const int*)d_in[1];
    float* out = (float*)d_out;
    int B = in_sizes[1];  // number of rows

    zero_out_kernel<<<1, 32>>>(out);

    const int threads = 256;
    int blocks = (B + threads - 1) / threads;
    loss_kernel<<<blocks, threads>>>(pred, tgt, out, B);
}